// round 12
// baseline (speedup 1.0000x reference)
#include <cuda_runtime.h>
#include <cuda_fp16.h>
#include <math.h>
#include <stdint.h>

#define NR 131072
#define EPS_N 1e-3f
#define LN_EPS 1e-5f

// ---- global scratch (allocation-free) ----
__device__ __half g_wd[128 * 512];
__device__ __half g_wl[512 * 512];
__device__ __half g_v2[(size_t)NR * 512];

// ---- helpers ----
__device__ __forceinline__ uint32_t smem_u32(const void* p) {
    uint32_t a;
    asm("{ .reg .u64 t; cvta.to.shared.u64 t, %1; cvt.u32.u64 %0, t; }" : "=r"(a) : "l"(p));
    return a;
}
__device__ __forceinline__ void mma_f16(float* c, uint32_t a0, uint32_t a1, uint32_t a2, uint32_t a3,
                                        uint32_t b0, uint32_t b1) {
    asm volatile("mma.sync.aligned.m16n8k16.row.col.f32.f16.f16.f32 "
                 "{%0,%1,%2,%3},{%4,%5,%6,%7},{%8,%9},{%0,%1,%2,%3};"
                 : "+f"(c[0]), "+f"(c[1]), "+f"(c[2]), "+f"(c[3])
                 : "r"(a0), "r"(a1), "r"(a2), "r"(a3), "r"(b0), "r"(b1));
}
#define LDSM4(R, A) \
    asm volatile("ldmatrix.sync.aligned.m8n8.x4.shared.b16 {%0,%1,%2,%3},[%4];" \
                 : "=r"((R)[0]), "=r"((R)[1]), "=r"((R)[2]), "=r"((R)[3]) : "r"(A))
#define CP16(dst, src) asm volatile("cp.async.ca.shared.global [%0],[%1],16;" :: "r"(dst), "l"(src) : "memory")
#define CPCOMMIT()     asm volatile("cp.async.commit_group;" ::: "memory")
#define CPWAIT0()      asm volatile("cp.async.wait_group 0;" ::: "memory")

// k1 row stride: 64 fp16 = 128B data + 16B pad = 144B
#define RST 144
// k2 row stride: 32 fp16 = 64B data + 16B pad = 80B
#define RS2 80

// ---------------- prep: convert weights to fp16 ----------------
__global__ void __launch_bounds__(256) kprep(const float* __restrict__ Wd,
                                             const float* __restrict__ Wl) {
    int i = blockIdx.x * 256 + threadIdx.x;
    if (i < 128 * 512) g_wd[i] = __float2half_rn(Wd[i]);
    if (i < 512 * 512) g_wl[i] = __float2half_rn(Wl[i]);
}

// ---------------- Kernel 1: HMMA GEMM1 + scalarizer epilogue ----------------
// CTA: 32 v-rows = 96 A-rows, N=128, K chunks of 64, double-buffered.
// 256 threads, warp grid 2(M)x4(N): warp tile 48x32. 2 CTAs/SM.
#define K1_A(b) (1536 + (b) * (96 * RST))
#define K1_B(b) (1536 + 2 * 96 * RST + (b) * (128 * RST))
#define VST 132
#define K1_SMEM (1536 + 2 * 96 * RST + 2 * 128 * RST)

__global__ void __launch_bounds__(256) k1_kernel(const float* __restrict__ v,
                                                 const float* __restrict__ We) {
    extern __shared__ char smem[];
    const uint32_t sb = smem_u32(smem);
    const int tid = threadIdx.x, wid = tid >> 5, lane = tid & 31;
    const int wm = wid & 1, wn = wid >> 1;          // 2(M) x 4(N)
    const int fr = lane >> 2, fc = lane & 3;
    const int lr = lane & 7, b8 = (lane >> 3) & 1, b16 = (lane >> 4) & 1;
    const int blk = blockIdx.x;
    const float* vbase = v + (size_t)blk * 96 * 512;

    float* sWe = (float*)smem;
    for (int i = tid; i < 384; i += 256) sWe[i] = We[i];

    const uint32_t aoff = (uint32_t)((wm * 48 + lr + b8 * 8) * RST + b16 * 16);
    const uint32_t boff = (uint32_t)((wn * 32 + lr + b8 * 8) * RST + b16 * 16);

    float acc[3][4][4];
#pragma unroll
    for (int m = 0; m < 3; m++)
#pragma unroll
        for (int n = 0; n < 4; n++)
#pragma unroll
            for (int j = 0; j < 4; j++) acc[m][n][j] = 0.f;

    float4 va[6];
    // prologue: chunk 0
#pragma unroll
    for (int t = 0; t < 4; t++) {
        int lin = tid + 256 * t;
        int r = lin >> 3, sg = lin & 7;
        CP16(sb + K1_B(0) + (uint32_t)(r * RST + sg * 16), g_wd + r * 512 + sg * 8);
    }
    CPCOMMIT();
#pragma unroll
    for (int t = 0; t < 6; t++) {
        int lin = tid + 256 * t;
        int g = lin >> 4, q = lin & 15;
        va[t] = *(const float4*)(vbase + (size_t)g * 512 + q * 4);
    }
#pragma unroll
    for (int t = 0; t < 6; t++) {
        int lin = tid + 256 * t;
        int g = lin >> 4, q = lin & 15;
        __half2 p0 = __floats2half2_rn(va[t].x, va[t].y);
        __half2 p1 = __floats2half2_rn(va[t].z, va[t].w);
        *(uint2*)(smem + K1_A(0) + g * RST + q * 8) =
            make_uint2(*(uint32_t*)&p0, *(uint32_t*)&p1);
    }
    CPWAIT0();
    __syncthreads();

    int cur = 0;
#pragma unroll
    for (int c = 0; c < 8; c++) {
        if (c < 7) {
            const int k0n = (c + 1) * 64;
#pragma unroll
            for (int t = 0; t < 4; t++) {
                int lin = tid + 256 * t;
                int r = lin >> 3, sg = lin & 7;
                CP16(sb + K1_B(cur ^ 1) + (uint32_t)(r * RST + sg * 16),
                     g_wd + r * 512 + k0n + sg * 8);
            }
            CPCOMMIT();
#pragma unroll
            for (int t = 0; t < 6; t++) {
                int lin = tid + 256 * t;
                int g = lin >> 4, q = lin & 15;
                va[t] = *(const float4*)(vbase + (size_t)g * 512 + k0n + q * 4);
            }
        }
        const uint32_t A = sb + K1_A(cur), B = sb + K1_B(cur);
#pragma unroll
        for (int ks = 0; ks < 4; ks++) {
            uint32_t a[3][4], b[2][4];
#pragma unroll
            for (int m = 0; m < 3; m++) LDSM4(a[m], A + aoff + m * 16 * RST + ks * 32);
#pragma unroll
            for (int p = 0; p < 2; p++) LDSM4(b[p], B + boff + p * 16 * RST + ks * 32);
#pragma unroll
            for (int m = 0; m < 3; m++)
#pragma unroll
                for (int n = 0; n < 4; n++)
                    mma_f16(acc[m][n], a[m][0], a[m][1], a[m][2], a[m][3],
                            b[n >> 1][n & 1], b[n >> 1][2 + (n & 1)]);
        }
        if (c < 7) {
#pragma unroll
            for (int t = 0; t < 6; t++) {
                int lin = tid + 256 * t;
                int g = lin >> 4, q = lin & 15;
                __half2 p0 = __floats2half2_rn(va[t].x, va[t].y);
                __half2 p1 = __floats2half2_rn(va[t].z, va[t].w);
                *(uint2*)(smem + K1_A(cur ^ 1) + g * RST + q * 8) =
                    make_uint2(*(uint32_t*)&p0, *(uint32_t*)&p1);
            }
            CPWAIT0();
        }
        __syncthreads();
        cur ^= 1;
    }

    // dump acc -> vred
    float* vred = (float*)(smem + 1536);
#pragma unroll
    for (int m = 0; m < 3; m++) {
        int row = wm * 48 + m * 16 + fr;
#pragma unroll
        for (int n = 0; n < 4; n++) {
            int col = wn * 32 + n * 8 + fc * 2;
            *(float2*)(vred + row * VST + col) = make_float2(acc[m][n][0], acc[m][n][1]);
            *(float2*)(vred + (row + 8) * VST + col) = make_float2(acc[m][n][2], acc[m][n][3]);
        }
    }
    __syncthreads();

    // ---- epilogue: norms, directions, projections -> v2 (fp16) ----
    float we[3][4];
#pragma unroll
    for (int e = 0; e < 3; e++)
#pragma unroll
        for (int c = 0; c < 4; c++) we[e][c] = sWe[e * 128 + lane + 32 * c];

    for (int t = 0; t < 4; t++) {
        int r = wid + 8 * t;
        size_t gr = (size_t)blk * 32 + r;
        float vr[3][4];
#pragma unroll
        for (int i = 0; i < 3; i++)
#pragma unroll
            for (int c = 0; c < 4; c++)
                vr[i][c] = vred[(r * 3 + i) * VST + lane + 32 * c];

        float d9[3][3];
#pragma unroll
        for (int i = 0; i < 3; i++)
#pragma unroll
            for (int e = 0; e < 3; e++) {
                float s = 0.f;
#pragma unroll
                for (int c = 0; c < 4; c++) s = fmaf(vr[i][c], we[e][c], s);
#pragma unroll
                for (int o = 16; o > 0; o >>= 1) s += __shfl_xor_sync(0xffffffffu, s, o);
                d9[i][e] = s;
            }
        float nd[3][3];
#pragma unroll
        for (int e = 0; e < 3; e++) {
            float dn = sqrtf(d9[0][e] * d9[0][e] + d9[1][e] * d9[1][e] + d9[2][e] * d9[2][e]);
            float inv = 1.f / (dn + EPS_N);
            nd[0][e] = d9[0][e] * inv;
            nd[1][e] = d9[1][e] * inv;
            nd[2][e] = d9[2][e] * inv;
        }
        __half* ov = g_v2 + gr * 512;
#pragma unroll
        for (int c = 0; c < 4; c++) {
            float n = sqrtf(vr[0][c] * vr[0][c] + vr[1][c] * vr[1][c] + vr[2][c] * vr[2][c]);
            float invn = 1.f / (n + EPS_N);
            int k = lane + 32 * c;
            ov[k] = __float2half_rn(n);
#pragma unroll
            for (int e = 0; e < 3; e++) {
                float p = (vr[0][c] * nd[0][e] + vr[1][c] * nd[1][e] + vr[2][c] * nd[2][e]) * invn;
                ov[128 + e * 128 + k] = __float2half_rn(p);
            }
        }
    }
}

// ---------------- Kernel 2: HMMA GEMM2 fused with LayerNorm+GELU ----------------
// CTA: 32 rows x full 512 cols. K chunks of 32, double-buffered.
// 256 threads, warp grid 1(M)x8(N): warp tile 32x64. 2 CTAs/SM.
#define K2_A(b) ((b) * (32 * RS2))
#define K2_B(b) (2 * 32 * RS2 + (b) * (512 * RS2))
#define K2_PSUM (2 * 32 * RS2 + 2 * 512 * RS2)
#define K2_PSQ (K2_PSUM + 1024)
#define K2_SMEM (K2_PSQ + 1024)

__global__ void __launch_bounds__(256, 2) k2_kernel(const float* __restrict__ bias,
                                                    const float* __restrict__ gamma,
                                                    const float* __restrict__ beta,
                                                    float* __restrict__ out) {
    extern __shared__ char smem[];
    const uint32_t sb = smem_u32(smem);
    const int tid = threadIdx.x, wid = tid >> 5, lane = tid & 31;
    const int wn = wid;                                // 1(M) x 8(N)
    const int fr = lane >> 2, fc = lane & 3;
    const int lr = lane & 7, b8 = (lane >> 3) & 1, b16 = (lane >> 4) & 1;
    const size_t row0 = (size_t)blockIdx.x * 32;

    // A: 32 rows x 4 segs(16B) = 128 -> tid<128, 1 per thread
    const int ar = tid >> 2, asg = tid & 3;
    const __half* asrc = g_v2 + (row0 + ar) * 512 + asg * 8;
    const uint32_t adst = (uint32_t)(ar * RS2 + asg * 16);

    const uint32_t aoff = (uint32_t)((lr + b8 * 8) * RS2 + b16 * 16);
    const uint32_t boff = (uint32_t)((wn * 64 + lr + b8 * 8) * RS2 + b16 * 16);

    float acc[2][8][4];
#pragma unroll
    for (int m = 0; m < 2; m++)
#pragma unroll
        for (int n = 0; n < 8; n++)
#pragma unroll
            for (int j = 0; j < 4; j++) acc[m][n][j] = 0.f;

    // prologue: chunk 0
    {
        if (tid < 128) CP16(sb + K2_A(0) + adst, asrc);
#pragma unroll
        for (int i = 0; i < 8; i++) {
            int lin = tid + 256 * i;
            int r = lin >> 2, sg = lin & 3;
            CP16(sb + K2_B(0) + (uint32_t)(r * RS2 + sg * 16), g_wl + (size_t)r * 512 + sg * 8);
        }
        CPCOMMIT();
        CPWAIT0();
        __syncthreads();
    }
    int cur = 0;
#pragma unroll
    for (int c = 0; c < 16; c++) {
        if (c < 15) {
            const int k0n = (c + 1) * 32;
            if (tid < 128) CP16(sb + K2_A(cur ^ 1) + adst, asrc + k0n);
#pragma unroll
            for (int i = 0; i < 8; i++) {
                int lin = tid + 256 * i;
                int r = lin >> 2, sg = lin & 3;
                CP16(sb + K2_B(cur ^ 1) + (uint32_t)(r * RS2 + sg * 16),
                     g_wl + (size_t)r * 512 + k0n + sg * 8);
            }
            CPCOMMIT();
        }
        const uint32_t A = sb + K2_A(cur), B = sb + K2_B(cur);
#pragma unroll
        for (int ks = 0; ks < 2; ks++) {
            uint32_t a[2][4], b[4][4];
#pragma unroll
            for (int m = 0; m < 2; m++) LDSM4(a[m], A + aoff + m * 16 * RS2 + ks * 32);
#pragma unroll
            for (int p = 0; p < 4; p++) LDSM4(b[p], B + boff + p * 16 * RS2 + ks * 32);
#pragma unroll
            for (int m = 0; m < 2; m++)
#pragma unroll
                for (int n = 0; n < 8; n++)
                    mma_f16(acc[m][n], a[m][0], a[m][1], a[m][2], a[m][3],
                            b[n >> 1][n & 1], b[n >> 1][2 + (n & 1)]);
        }
        if (c < 15) CPWAIT0();
        __syncthreads();
        cur ^= 1;
    }

    // ---- fused epilogue: bias + LayerNorm + exact GELU ----
#pragma unroll
    for (int n = 0; n < 8; n++) {
        int col = wn * 64 + n * 8 + fc * 2;
        float2 bb = *(const float2*)(bias + col);
#pragma unroll
        for (int m = 0; m < 2; m++) {
            acc[m][n][0] += bb.x; acc[m][n][1] += bb.y;
            acc[m][n][2] += bb.x; acc[m][n][3] += bb.y;
        }
    }
    float* psum = (float*)(smem + K2_PSUM);
    float* psq  = (float*)(smem + K2_PSQ);
#pragma unroll
    for (int m = 0; m < 2; m++)
#pragma unroll
        for (int h = 0; h < 2; h++) {
            float s = 0.f, q = 0.f;
#pragma unroll
            for (int n = 0; n < 8; n++) {
                float e0 = acc[m][n][h * 2], e1 = acc[m][n][h * 2 + 1];
                s += e0 + e1;
                q += e0 * e0 + e1 * e1;
            }
            s += __shfl_xor_sync(0xffffffffu, s, 1);
            s += __shfl_xor_sync(0xffffffffu, s, 2);
            q += __shfl_xor_sync(0xffffffffu, q, 1);
            q += __shfl_xor_sync(0xffffffffu, q, 2);
            int rr = m * 16 + h * 8 + fr;
            if (fc == 0) { psum[wn * 32 + rr] = s; psq[wn * 32 + rr] = q; }
        }
    __syncthreads();

    const float invs2 = 0.70710678118654752f;
#pragma unroll
    for (int m = 0; m < 2; m++)
#pragma unroll
        for (int h = 0; h < 2; h++) {
            int rr = m * 16 + h * 8 + fr;
            float S = 0.f, Q = 0.f;
#pragma unroll
            for (int w = 0; w < 8; w++) { S += psum[w * 32 + rr]; Q += psq[w * 32 + rr]; }
            float mu = S * (1.f / 512.f);
            float var = Q * (1.f / 512.f) - mu * mu;
            float rstd = rsqrtf(var + LN_EPS);
            size_t orow = (row0 + rr) * 512;
#pragma unroll
            for (int n = 0; n < 8; n++) {
                int col = wn * 64 + n * 8 + fc * 2;
                float2 g2 = *(const float2*)(gamma + col);
                float2 b2 = *(const float2*)(beta + col);
                float y0 = (acc[m][n][h * 2] - mu) * rstd * g2.x + b2.x;
                float y1 = (acc[m][n][h * 2 + 1] - mu) * rstd * g2.y + b2.y;
                float o0 = y0 * 0.5f * (1.f + erff(y0 * invs2));
                float o1 = y1 * 0.5f * (1.f + erff(y1 * invs2));
                *(float2*)(out + orow + col) = make_float2(o0, o1);
            }
        }
}

// ---------------- launch ----------------
extern "C" void kernel_launch(void* const* d_in, const int* in_sizes, int n_in,
                              void* d_out, int out_size) {
    const float* v     = (const float*)d_in[0];
    const float* Wd    = (const float*)d_in[1];
    const float* We    = (const float*)d_in[2];
    const float* Wl    = (const float*)d_in[3];
    const float* bl    = (const float*)d_in[4];
    const float* gamma = (const float*)d_in[5];
    const float* beta  = (const float*)d_in[6];
    float* out = (float*)d_out;

    cudaFuncSetAttribute(k1_kernel, cudaFuncAttributeMaxDynamicSharedMemorySize, K1_SMEM);
    cudaFuncSetAttribute(k2_kernel, cudaFuncAttributeMaxDynamicSharedMemorySize, K2_SMEM);

    kprep<<<1024, 256>>>(Wd, Wl);
    k1_kernel<<<NR / 32, 256, K1_SMEM>>>(v, We);
    k2_kernel<<<NR / 32, 256, K2_SMEM>>>(bl, gamma, beta, out);
}

// round 13
// speedup vs baseline: 1.1978x; 1.1978x over previous
#include <cuda_runtime.h>
#include <cuda_fp16.h>
#include <math.h>
#include <stdint.h>

#define NR 131072
#define EPS_N 1e-3f
#define LN_EPS 1e-5f

// ---- global scratch (allocation-free) ----
__device__ __half g_wd[128 * 512];
__device__ __half g_wl[512 * 512];
__device__ __half g_v2[(size_t)NR * 512];

// ---- helpers ----
__device__ __forceinline__ uint32_t smem_u32(const void* p) {
    uint32_t a;
    asm("{ .reg .u64 t; cvta.to.shared.u64 t, %1; cvt.u32.u64 %0, t; }" : "=r"(a) : "l"(p));
    return a;
}
__device__ __forceinline__ void mma_f16(float* c, uint32_t a0, uint32_t a1, uint32_t a2, uint32_t a3,
                                        uint32_t b0, uint32_t b1) {
    asm volatile("mma.sync.aligned.m16n8k16.row.col.f32.f16.f16.f32 "
                 "{%0,%1,%2,%3},{%4,%5,%6,%7},{%8,%9},{%0,%1,%2,%3};"
                 : "+f"(c[0]), "+f"(c[1]), "+f"(c[2]), "+f"(c[3])
                 : "r"(a0), "r"(a1), "r"(a2), "r"(a3), "r"(b0), "r"(b1));
}
#define LDSM4(R, A) \
    asm volatile("ldmatrix.sync.aligned.m8n8.x4.shared.b16 {%0,%1,%2,%3},[%4];" \
                 : "=r"((R)[0]), "=r"((R)[1]), "=r"((R)[2]), "=r"((R)[3]) : "r"(A))
#define CP16(dst, src) asm volatile("cp.async.ca.shared.global [%0],[%1],16;" :: "r"(dst), "l"(src) : "memory")
#define CPCOMMIT()     asm volatile("cp.async.commit_group;" ::: "memory")
#define CPWAIT0()      asm volatile("cp.async.wait_group 0;" ::: "memory")
#define CLUSTER_SYNC() do { \
    asm volatile("barrier.cluster.arrive.aligned;" ::: "memory"); \
    asm volatile("barrier.cluster.wait.aligned;" ::: "memory"); \
} while (0)

// row stride: 64 fp16 = 128B data + 16B pad = 144B (conflict-free ldmatrix)
#define RST 144

// ---------------- prep: convert weights to fp16 ----------------
__global__ void __launch_bounds__(256) kprep(const float* __restrict__ Wd,
                                             const float* __restrict__ Wl) {
    int i = blockIdx.x * 256 + threadIdx.x;
    if (i < 128 * 512) g_wd[i] = __float2half_rn(Wd[i]);
    if (i < 512 * 512) g_wl[i] = __float2half_rn(Wl[i]);
}

// ---------------- Kernel 1: HMMA GEMM1 + scalarizer epilogue ----------------
// (unchanged from R10 best: 32 v-rows, K chunks 64, 256 threads, 2 CTAs/SM)
#define K1_A(b) (1536 + (b) * (96 * RST))
#define K1_B(b) (1536 + 2 * 96 * RST + (b) * (128 * RST))
#define VST 132
#define K1_SMEM (1536 + 2 * 96 * RST + 2 * 128 * RST)

__global__ void __launch_bounds__(256) k1_kernel(const float* __restrict__ v,
                                                 const float* __restrict__ We) {
    extern __shared__ char smem[];
    const uint32_t sb = smem_u32(smem);
    const int tid = threadIdx.x, wid = tid >> 5, lane = tid & 31;
    const int wm = wid & 1, wn = wid >> 1;          // 2(M) x 4(N)
    const int fr = lane >> 2, fc = lane & 3;
    const int lr = lane & 7, b8 = (lane >> 3) & 1, b16 = (lane >> 4) & 1;
    const int blk = blockIdx.x;
    const float* vbase = v + (size_t)blk * 96 * 512;

    float* sWe = (float*)smem;
    for (int i = tid; i < 384; i += 256) sWe[i] = We[i];

    const uint32_t aoff = (uint32_t)((wm * 48 + lr + b8 * 8) * RST + b16 * 16);
    const uint32_t boff = (uint32_t)((wn * 32 + lr + b8 * 8) * RST + b16 * 16);

    float acc[3][4][4];
#pragma unroll
    for (int m = 0; m < 3; m++)
#pragma unroll
        for (int n = 0; n < 4; n++)
#pragma unroll
            for (int j = 0; j < 4; j++) acc[m][n][j] = 0.f;

    float4 va[6];
#pragma unroll
    for (int t = 0; t < 4; t++) {
        int lin = tid + 256 * t;
        int r = lin >> 3, sg = lin & 7;
        CP16(sb + K1_B(0) + (uint32_t)(r * RST + sg * 16), g_wd + r * 512 + sg * 8);
    }
    CPCOMMIT();
#pragma unroll
    for (int t = 0; t < 6; t++) {
        int lin = tid + 256 * t;
        int g = lin >> 4, q = lin & 15;
        va[t] = *(const float4*)(vbase + (size_t)g * 512 + q * 4);
    }
#pragma unroll
    for (int t = 0; t < 6; t++) {
        int lin = tid + 256 * t;
        int g = lin >> 4, q = lin & 15;
        __half2 p0 = __floats2half2_rn(va[t].x, va[t].y);
        __half2 p1 = __floats2half2_rn(va[t].z, va[t].w);
        *(uint2*)(smem + K1_A(0) + g * RST + q * 8) =
            make_uint2(*(uint32_t*)&p0, *(uint32_t*)&p1);
    }
    CPWAIT0();
    __syncthreads();

    int cur = 0;
#pragma unroll
    for (int c = 0; c < 8; c++) {
        if (c < 7) {
            const int k0n = (c + 1) * 64;
#pragma unroll
            for (int t = 0; t < 4; t++) {
                int lin = tid + 256 * t;
                int r = lin >> 3, sg = lin & 7;
                CP16(sb + K1_B(cur ^ 1) + (uint32_t)(r * RST + sg * 16),
                     g_wd + r * 512 + k0n + sg * 8);
            }
            CPCOMMIT();
#pragma unroll
            for (int t = 0; t < 6; t++) {
                int lin = tid + 256 * t;
                int g = lin >> 4, q = lin & 15;
                va[t] = *(const float4*)(vbase + (size_t)g * 512 + k0n + q * 4);
            }
        }
        const uint32_t A = sb + K1_A(cur), B = sb + K1_B(cur);
#pragma unroll
        for (int ks = 0; ks < 4; ks++) {
            uint32_t a[3][4], b[2][4];
#pragma unroll
            for (int m = 0; m < 3; m++) LDSM4(a[m], A + aoff + m * 16 * RST + ks * 32);
#pragma unroll
            for (int p = 0; p < 2; p++) LDSM4(b[p], B + boff + p * 16 * RST + ks * 32);
#pragma unroll
            for (int m = 0; m < 3; m++)
#pragma unroll
                for (int n = 0; n < 4; n++)
                    mma_f16(acc[m][n], a[m][0], a[m][1], a[m][2], a[m][3],
                            b[n >> 1][n & 1], b[n >> 1][2 + (n & 1)]);
        }
        if (c < 7) {
#pragma unroll
            for (int t = 0; t < 6; t++) {
                int lin = tid + 256 * t;
                int g = lin >> 4, q = lin & 15;
                __half2 p0 = __floats2half2_rn(va[t].x, va[t].y);
                __half2 p1 = __floats2half2_rn(va[t].z, va[t].w);
                *(uint2*)(smem + K1_A(cur ^ 1) + g * RST + q * 8) =
                    make_uint2(*(uint32_t*)&p0, *(uint32_t*)&p1);
            }
            CPWAIT0();
        }
        __syncthreads();
        cur ^= 1;
    }

    float* vred = (float*)(smem + 1536);
#pragma unroll
    for (int m = 0; m < 3; m++) {
        int row = wm * 48 + m * 16 + fr;
#pragma unroll
        for (int n = 0; n < 4; n++) {
            int col = wn * 32 + n * 8 + fc * 2;
            *(float2*)(vred + row * VST + col) = make_float2(acc[m][n][0], acc[m][n][1]);
            *(float2*)(vred + (row + 8) * VST + col) = make_float2(acc[m][n][2], acc[m][n][3]);
        }
    }
    __syncthreads();

    float we[3][4];
#pragma unroll
    for (int e = 0; e < 3; e++)
#pragma unroll
        for (int c = 0; c < 4; c++) we[e][c] = sWe[e * 128 + lane + 32 * c];

    for (int t = 0; t < 4; t++) {
        int r = wid + 8 * t;
        size_t gr = (size_t)blk * 32 + r;
        float vr[3][4];
#pragma unroll
        for (int i = 0; i < 3; i++)
#pragma unroll
            for (int c = 0; c < 4; c++)
                vr[i][c] = vred[(r * 3 + i) * VST + lane + 32 * c];

        float d9[3][3];
#pragma unroll
        for (int i = 0; i < 3; i++)
#pragma unroll
            for (int e = 0; e < 3; e++) {
                float s = 0.f;
#pragma unroll
                for (int c = 0; c < 4; c++) s = fmaf(vr[i][c], we[e][c], s);
#pragma unroll
                for (int o = 16; o > 0; o >>= 1) s += __shfl_xor_sync(0xffffffffu, s, o);
                d9[i][e] = s;
            }
        float nd[3][3];
#pragma unroll
        for (int e = 0; e < 3; e++) {
            float dn = sqrtf(d9[0][e] * d9[0][e] + d9[1][e] * d9[1][e] + d9[2][e] * d9[2][e]);
            float inv = 1.f / (dn + EPS_N);
            nd[0][e] = d9[0][e] * inv;
            nd[1][e] = d9[1][e] * inv;
            nd[2][e] = d9[2][e] * inv;
        }
        __half* ov = g_v2 + gr * 512;
#pragma unroll
        for (int c = 0; c < 4; c++) {
            float n = sqrtf(vr[0][c] * vr[0][c] + vr[1][c] * vr[1][c] + vr[2][c] * vr[2][c]);
            float invn = 1.f / (n + EPS_N);
            int k = lane + 32 * c;
            ov[k] = __float2half_rn(n);
#pragma unroll
            for (int e = 0; e < 3; e++) {
                float p = (vr[0][c] * nd[0][e] + vr[1][c] * nd[1][e] + vr[2][c] * nd[2][e]) * invn;
                ov[128 + e * 128 + k] = __float2half_rn(p);
            }
        }
    }
}

// ---------------- Kernel 2: cluster-pair HMMA GEMM2 + LayerNorm + GELU ----------------
// Cluster of 2 CTAs shares one 64-row block; CTA rank handles cols [rank*256, +256).
// 256 threads/CTA, warp grid 1(M)x8(N): warp tile 64x32. K chunks 64. 2 CTAs/SM.
#define K2_A(b)  ((b) * (64 * RST))
#define K2_B(b)  (2 * 64 * RST + (b) * (256 * RST))
#define K2_PSUM  (2 * 64 * RST + 2 * 256 * RST)      // float[8][64]
#define K2_PSQ   (K2_PSUM + 2048)                    // float[8][64]
#define K2_XSUM  (K2_PSQ + 2048)                     // float[64]
#define K2_XSQ   (K2_XSUM + 256)                     // float[64]
#define K2_SMEM  (K2_XSQ + 256)

__global__ void __launch_bounds__(256, 2) __cluster_dims__(2, 1, 1)
k2_kernel(const float* __restrict__ bias,
          const float* __restrict__ gamma,
          const float* __restrict__ beta,
          float* __restrict__ out) {
    extern __shared__ char smem[];
    const uint32_t sb = smem_u32(smem);
    const int tid = threadIdx.x, wid = tid >> 5, lane = tid & 31;
    const int wn = wid;                               // 8 warps across 256 cols
    const int fr = lane >> 2, fc = lane & 3;
    const int lr = lane & 7, b8 = (lane >> 3) & 1, b16 = (lane >> 4) & 1;
    const uint32_t rank = (uint32_t)(blockIdx.x & 1);
    const size_t row0 = (size_t)(blockIdx.x >> 1) * 64;
    const int colbase = (int)rank * 256;

    const uint32_t aoff = (uint32_t)((lr + b8 * 8) * RST + b16 * 16);
    const uint32_t boff = (uint32_t)((wn * 32 + lr + b8 * 8) * RST + b16 * 16);

    float acc[4][4][4];
#pragma unroll
    for (int m = 0; m < 4; m++)
#pragma unroll
        for (int n = 0; n < 4; n++)
#pragma unroll
            for (int j = 0; j < 4; j++) acc[m][n][j] = 0.f;

    // prologue: chunk 0
    {
#pragma unroll
        for (int t = 0; t < 2; t++) {       // A: 64 rows x 8 segs = 512 jobs
            int lin = tid + 256 * t;
            int r = lin >> 3, sg = lin & 7;
            CP16(sb + K2_A(0) + (uint32_t)(r * RST + sg * 16),
                 g_v2 + (row0 + r) * 512 + sg * 8);
        }
#pragma unroll
        for (int t = 0; t < 8; t++) {       // B: 256 rows x 8 segs = 2048 jobs
            int lin = tid + 256 * t;
            int r = lin >> 3, sg = lin & 7;
            CP16(sb + K2_B(0) + (uint32_t)(r * RST + sg * 16),
                 g_wl + (size_t)(colbase + r) * 512 + sg * 8);
        }
        CPCOMMIT();
        CPWAIT0();
        __syncthreads();
    }
    int cur = 0;
#pragma unroll
    for (int c = 0; c < 8; c++) {
        if (c < 7) {
            const int k0n = (c + 1) * 64;
#pragma unroll
            for (int t = 0; t < 2; t++) {
                int lin = tid + 256 * t;
                int r = lin >> 3, sg = lin & 7;
                CP16(sb + K2_A(cur ^ 1) + (uint32_t)(r * RST + sg * 16),
                     g_v2 + (row0 + r) * 512 + k0n + sg * 8);
            }
#pragma unroll
            for (int t = 0; t < 8; t++) {
                int lin = tid + 256 * t;
                int r = lin >> 3, sg = lin & 7;
                CP16(sb + K2_B(cur ^ 1) + (uint32_t)(r * RST + sg * 16),
                     g_wl + (size_t)(colbase + r) * 512 + k0n + sg * 8);
            }
            CPCOMMIT();
        }
        const uint32_t A = sb + K2_A(cur), B = sb + K2_B(cur);
#pragma unroll
        for (int ks = 0; ks < 4; ks++) {
            uint32_t a[4][4], b[2][4];
#pragma unroll
            for (int m = 0; m < 4; m++) LDSM4(a[m], A + aoff + m * 16 * RST + ks * 32);
#pragma unroll
            for (int p = 0; p < 2; p++) LDSM4(b[p], B + boff + p * 16 * RST + ks * 32);
#pragma unroll
            for (int m = 0; m < 4; m++)
#pragma unroll
                for (int n = 0; n < 4; n++)
                    mma_f16(acc[m][n], a[m][0], a[m][1], a[m][2], a[m][3],
                            b[n >> 1][n & 1], b[n >> 1][2 + (n & 1)]);
        }
        if (c < 7) CPWAIT0();
        __syncthreads();
        cur ^= 1;
    }

    // ---- epilogue: bias, partial LN stats, cluster exchange, LN+GELU ----
#pragma unroll
    for (int n = 0; n < 4; n++) {
        int col = colbase + wn * 32 + n * 8 + fc * 2;
        float2 bb = *(const float2*)(bias + col);
#pragma unroll
        for (int m = 0; m < 4; m++) {
            acc[m][n][0] += bb.x; acc[m][n][1] += bb.y;
            acc[m][n][2] += bb.x; acc[m][n][3] += bb.y;
        }
    }
    float* psum = (float*)(smem + K2_PSUM);
    float* psq  = (float*)(smem + K2_PSQ);
#pragma unroll
    for (int m = 0; m < 4; m++)
#pragma unroll
        for (int h = 0; h < 2; h++) {
            float s = 0.f, q = 0.f;
#pragma unroll
            for (int n = 0; n < 4; n++) {
                float e0 = acc[m][n][h * 2], e1 = acc[m][n][h * 2 + 1];
                s += e0 + e1;
                q += e0 * e0 + e1 * e1;
            }
            s += __shfl_xor_sync(0xffffffffu, s, 1);
            s += __shfl_xor_sync(0xffffffffu, s, 2);
            q += __shfl_xor_sync(0xffffffffu, q, 1);
            q += __shfl_xor_sync(0xffffffffu, q, 2);
            int rr = m * 16 + h * 8 + fr;
            if (fc == 0) { psum[wn * 64 + rr] = s; psq[wn * 64 + rr] = q; }
        }
    __syncthreads();
    // combine 8 warps -> per-row partials for this CTA's 256 cols
    if (tid < 64) {
        float S = 0.f, Q = 0.f;
#pragma unroll
        for (int w = 0; w < 8; w++) { S += psum[w * 64 + tid]; Q += psq[w * 64 + tid]; }
        ((float*)(smem + K2_XSUM))[tid] = S;
        ((float*)(smem + K2_XSQ))[tid] = Q;
    }
    // make partials visible cluster-wide, then read peer's
    CLUSTER_SYNC();

    const uint32_t peer = rank ^ 1u;
    const float invs2 = 0.70710678118654752f;
#pragma unroll
    for (int m = 0; m < 4; m++)
#pragma unroll
        for (int h = 0; h < 2; h++) {
            int rr = m * 16 + h * 8 + fr;
            float S = ((float*)(smem + K2_XSUM))[rr];
            float Q = ((float*)(smem + K2_XSQ))[rr];
            float pS, pQ;
            uint32_t la = sb + K2_XSUM + (uint32_t)(rr * 4), ra;
            asm("mapa.shared::cluster.u32 %0, %1, %2;" : "=r"(ra) : "r"(la), "r"(peer));
            asm("ld.shared::cluster.f32 %0, [%1];" : "=f"(pS) : "r"(ra));
            la = sb + K2_XSQ + (uint32_t)(rr * 4);
            asm("mapa.shared::cluster.u32 %0, %1, %2;" : "=r"(ra) : "r"(la), "r"(peer));
            asm("ld.shared::cluster.f32 %0, [%1];" : "=f"(pQ) : "r"(ra));
            S += pS; Q += pQ;
            float mu = S * (1.f / 512.f);
            float var = Q * (1.f / 512.f) - mu * mu;
            float rstd = rsqrtf(var + LN_EPS);
            size_t orow = (row0 + rr) * 512;
#pragma unroll
            for (int n = 0; n < 4; n++) {
                int col = colbase + wn * 32 + n * 8 + fc * 2;
                float2 g2 = *(const float2*)(gamma + col);
                float2 b2 = *(const float2*)(beta + col);
                float y0 = (acc[m][n][h * 2] - mu) * rstd * g2.x + b2.x;
                float y1 = (acc[m][n][h * 2 + 1] - mu) * rstd * g2.y + b2.y;
                float o0 = y0 * 0.5f * (1.f + erff(y0 * invs2));
                float o1 = y1 * 0.5f * (1.f + erff(y1 * invs2));
                *(float2*)(out + orow + col) = make_float2(o0, o1);
            }
        }
    // peer may still be reading our partials: hold smem until both sides done
    CLUSTER_SYNC();
}

// ---------------- launch ----------------
extern "C" void kernel_launch(void* const* d_in, const int* in_sizes, int n_in,
                              void* d_out, int out_size) {
    const float* v     = (const float*)d_in[0];
    const float* Wd    = (const float*)d_in[1];
    const float* We    = (const float*)d_in[2];
    const float* Wl    = (const float*)d_in[3];
    const float* bl    = (const float*)d_in[4];
    const float* gamma = (const float*)d_in[5];
    const float* beta  = (const float*)d_in[6];
    float* out = (float*)d_out;

    cudaFuncSetAttribute(k1_kernel, cudaFuncAttributeMaxDynamicSharedMemorySize, K1_SMEM);
    cudaFuncSetAttribute(k2_kernel, cudaFuncAttributeMaxDynamicSharedMemorySize, K2_SMEM);

    kprep<<<1024, 256>>>(Wd, Wl);
    k1_kernel<<<NR / 32, 256, K1_SMEM>>>(v, We);
    k2_kernel<<<(NR / 64) * 2, 256, K2_SMEM>>>(bl, gamma, beta, out);
}